// round 2
// baseline (speedup 1.0000x reference)
#include <cuda_runtime.h>
#include <math.h>

#define Nn   50000
#define Ee   800000
#define EPt  850000   // E + N self loops
#define Gg   64

// ---------------- scratch (static __device__, no allocations) ----------------
__device__ __align__(16) float    g_h1   [(size_t)Nn*128];
__device__ __align__(16) float    g_out1 [(size_t)Nn*128];
__device__ __align__(16) float    g_h2   [(size_t)Nn*64];
__device__ __align__(16) float    g_out2 [(size_t)Nn*64];
__device__ __align__(16) float    g_asrc1[Nn*4];
__device__ __align__(16) float    g_adst1[Nn*4];
__device__ __align__(16) float    g_asrc2[Nn];
__device__ __align__(16) float    g_adst2[Nn];
__device__ __align__(16) float    g_alpha1[(size_t)EPt*4];   // alpha, then ex
__device__ __align__(16) float    g_alpha2[EPt];
__device__ __align__(16) float    g_aedge2[EPt];
__device__ __align__(16) int      g_srcs [EPt];
__device__ __align__(16) int      g_dsts [EPt];
__device__ __align__(16) unsigned g_amax1[Nn*4];
__device__ __align__(16) float    g_den1 [Nn*4];
__device__ __align__(16) unsigned g_amax2[Nn];
__device__ __align__(16) float    g_den2 [Nn];
__device__ __align__(16) float    g_sum_ea[16];
__device__ __align__(16) float    g_v1[64];
__device__ __align__(16) float    g_v2[16];
__device__ __align__(16) float    g_lae1[4];
__device__ __align__(16) float    g_lae2[1];
__device__ __align__(16) float    g_pool[Gg*64];
__device__ __align__(16) int      g_cnt [Gg];

// monotone float<->uint key for atomicMax on floats (handles negatives)
__device__ __forceinline__ unsigned fkey(float f){
    unsigned u = __float_as_uint(f);
    return (u & 0x80000000u) ? ~u : (u | 0x80000000u);
}
__device__ __forceinline__ float funkey(unsigned k){
    return (k & 0x80000000u) ? __uint_as_float(k & 0x7FFFFFFFu)
                             : __uint_as_float(~k);
}
__device__ __forceinline__ float lrelu(float x){ return x > 0.f ? x : 0.2f*x; }

// ---------------- 1. sum of edge_attr rows (for self-loop fill) ----------------
__global__ void k_sum_ea(const float* __restrict__ ea){
    float acc[16];
#pragma unroll
    for(int i=0;i<16;i++) acc[i]=0.f;
    int stride = gridDim.x*blockDim.x;
    for(int e = blockIdx.x*blockDim.x + threadIdx.x; e < Ee; e += stride){
        const float4* r = (const float4*)(ea + (size_t)e*16);
        float4 a=__ldg(r), b=__ldg(r+1), c=__ldg(r+2), d=__ldg(r+3);
        acc[0]+=a.x; acc[1]+=a.y; acc[2]+=a.z; acc[3]+=a.w;
        acc[4]+=b.x; acc[5]+=b.y; acc[6]+=b.z; acc[7]+=b.w;
        acc[8]+=c.x; acc[9]+=c.y; acc[10]+=c.z; acc[11]+=c.w;
        acc[12]+=d.x; acc[13]+=d.y; acc[14]+=d.z; acc[15]+=d.w;
    }
#pragma unroll
    for(int off=16; off; off>>=1)
#pragma unroll
        for(int i=0;i<16;i++) acc[i] += __shfl_xor_sync(0xffffffffu, acc[i], off);
    if((threadIdx.x & 31)==0)
#pragma unroll
        for(int i=0;i<16;i++) atomicAdd(&g_sum_ea[i], acc[i]);
}

// ---------------- 2. tiny setup: v1, v2, self-loop a_edge consts ----------------
__global__ void k_setup(const float* __restrict__ We1, const float* __restrict__ ae1,
                        const float* __restrict__ We2, const float* __restrict__ ae2){
    __shared__ float mean[16];
    int t = threadIdx.x;
    if(t < 16) mean[t] = g_sum_ea[t] * (1.0f/(float)Ee);
    {   // v1[h][d] = sum_c We1[d,h*32+c]*att_edge1[h,c]
        int h = t >> 4, d = t & 15;
        float s = 0.f;
        for(int c=0;c<32;c++) s += We1[d*128 + h*32 + c] * ae1[h*32 + c];
        g_v1[h*16 + d] = s;
    }
    if(t < 16){ // v2[d] = sum_c We2[d,c]*att_edge2[c]
        float s = 0.f;
        for(int c=0;c<64;c++) s += We2[t*64 + c] * ae2[c];
        g_v2[t] = s;
    }
    __syncthreads();
    if(t < 4){
        float s = 0.f;
        for(int d=0;d<16;d++) s += mean[d]*g_v1[t*16+d];
        g_lae1[t] = s;
    }
    if(t == 32){
        float s = 0.f;
        for(int d=0;d<16;d++) s += mean[d]*g_v2[d];
        g_lae2[0] = s;
    }
}

// ---------------- 3. register-tiled SGEMM (K=128 fixed), optional fused ELU on A ----------------
// C[M,NC] = act(A[M,128]) @ W[128,NC];  act = identity or elu(a + abias[k])
template<int NC, bool ELU>
__global__ __launch_bounds__(256) void k_gemm(const float* __restrict__ A,
                                              const float* __restrict__ W,
                                              const float* __restrict__ abias,
                                              float* __restrict__ C, int M){
    constexpr int CPT = NC/16;                 // cols per thread (8 or 4)
    __shared__ float As[64*36];                // 64 rows x 32 k (pad 36)
    __shared__ float Ws[32*NC];
    const int t  = threadIdx.x;
    const int rg = t >> 4, cg = t & 15;
    const int r0 = blockIdx.x * 64;
    float acc[4][CPT];
#pragma unroll
    for(int i=0;i<4;i++)
#pragma unroll
        for(int j=0;j<CPT;j++) acc[i][j]=0.f;

    for(int kc=0; kc<128; kc+=32){
        // stage A chunk 64x32
#pragma unroll
        for(int i=0;i<2;i++){
            int f = t + i*256; int r = f>>3; int c4 = f&7;
            float4 v = make_float4(0.f,0.f,0.f,0.f);
            if(r0 + r < M) v = __ldg((const float4*)&A[(size_t)(r0+r)*128 + kc + c4*4]);
            if(ELU){
                float4 bb = __ldg((const float4*)&abias[kc + c4*4]);
                v.x += bb.x; v.y += bb.y; v.z += bb.z; v.w += bb.w;
                v.x = v.x>0.f ? v.x : expm1f(v.x);
                v.y = v.y>0.f ? v.y : expm1f(v.y);
                v.z = v.z>0.f ? v.z : expm1f(v.z);
                v.w = v.w>0.f ? v.w : expm1f(v.w);
            }
            float* dst = &As[r*36 + c4*4];
            dst[0]=v.x; dst[1]=v.y; dst[2]=v.z; dst[3]=v.w;
        }
        // stage W chunk 32xNC
#pragma unroll
        for(int f=t; f < 32*NC/4; f += 256){
            int k = f/(NC/4); int c = f%(NC/4);
            *(float4*)&Ws[k*NC + c*4] = __ldg((const float4*)&W[(size_t)(kc+k)*NC + c*4]);
        }
        __syncthreads();
#pragma unroll 4
        for(int kk=0; kk<32; kk++){
            float a0 = As[(rg*4+0)*36+kk];
            float a1 = As[(rg*4+1)*36+kk];
            float a2 = As[(rg*4+2)*36+kk];
            float a3 = As[(rg*4+3)*36+kk];
            float4 b0 = *(const float4*)&Ws[kk*NC + cg*CPT];
            acc[0][0]+=a0*b0.x; acc[0][1]+=a0*b0.y; acc[0][2]+=a0*b0.z; acc[0][3]+=a0*b0.w;
            acc[1][0]+=a1*b0.x; acc[1][1]+=a1*b0.y; acc[1][2]+=a1*b0.z; acc[1][3]+=a1*b0.w;
            acc[2][0]+=a2*b0.x; acc[2][1]+=a2*b0.y; acc[2][2]+=a2*b0.z; acc[2][3]+=a2*b0.w;
            acc[3][0]+=a3*b0.x; acc[3][1]+=a3*b0.y; acc[3][2]+=a3*b0.z; acc[3][3]+=a3*b0.w;
            if constexpr (CPT == 8){
                float4 b1 = *(const float4*)&Ws[kk*NC + cg*CPT + 4];
                acc[0][4]+=a0*b1.x; acc[0][5]+=a0*b1.y; acc[0][6]+=a0*b1.z; acc[0][7]+=a0*b1.w;
                acc[1][4]+=a1*b1.x; acc[1][5]+=a1*b1.y; acc[1][6]+=a1*b1.z; acc[1][7]+=a1*b1.w;
                acc[2][4]+=a2*b1.x; acc[2][5]+=a2*b1.y; acc[2][6]+=a2*b1.z; acc[2][7]+=a2*b1.w;
                acc[3][4]+=a3*b1.x; acc[3][5]+=a3*b1.y; acc[3][6]+=a3*b1.z; acc[3][7]+=a3*b1.w;
            }
        }
        __syncthreads();
    }
#pragma unroll
    for(int i=0;i<4;i++){
        int row = r0 + rg*4 + i;
        if(row < M){
#pragma unroll
            for(int j4=0; j4<CPT; j4+=4){
                float4 v = make_float4(acc[i][j4],acc[i][j4+1],acc[i][j4+2],acc[i][j4+3]);
                *(float4*)&C[(size_t)row*NC + cg*CPT + j4] = v;
            }
        }
    }
}

// ---------------- 4. per-node attention scalars, layer 1 ----------------
__global__ void k_a1(const float* __restrict__ as1, const float* __restrict__ ad1){
    int idx = blockIdx.x*blockDim.x + threadIdx.x;
    if(idx >= Nn*4) return;
    int n = idx >> 2, h = idx & 3;
    const float4* hp = (const float4*)&g_h1[(size_t)n*128 + h*32];
    const float4* sp = (const float4*)&as1[h*32];
    const float4* dp = (const float4*)&ad1[h*32];
    float s=0.f, d=0.f;
#pragma unroll
    for(int i=0;i<8;i++){
        float4 hv = hp[i], sv = __ldg(&sp[i]), dv = __ldg(&dp[i]);
        s += hv.x*sv.x + hv.y*sv.y + hv.z*sv.z + hv.w*sv.w;
        d += hv.x*dv.x + hv.y*dv.y + hv.z*dv.z + hv.w*dv.w;
    }
    g_asrc1[idx]=s; g_adst1[idx]=d;
}

// ---------------- 5. edge alpha (layer1) + a_edge2 stash + src/dst copy ----------------
__global__ void k_alpha1(const int* __restrict__ ei, const float* __restrict__ ea){
    __shared__ float sv1[64], sv2[16], slae1[4], slae2;
    int t = threadIdx.x;
    if(t < 64) sv1[t] = g_v1[t];
    if(t < 16) sv2[t] = g_v2[t];
    if(t < 4)  slae1[t] = g_lae1[t];
    if(t == 0) slae2 = g_lae2[0];
    __syncthreads();
    int e = blockIdx.x*blockDim.x + t;
    if(e >= EPt) return;
    int s, d; float ae[4], ae2;
    if(e < Ee){
        s = __ldg(&ei[e]); d = __ldg(&ei[Ee + e]);
        float r[16];
        const float4* rp = (const float4*)(ea + (size_t)e*16);
        ((float4*)r)[0]=__ldg(rp); ((float4*)r)[1]=__ldg(rp+1);
        ((float4*)r)[2]=__ldg(rp+2); ((float4*)r)[3]=__ldg(rp+3);
#pragma unroll
        for(int h=0;h<4;h++){
            float a=0.f;
#pragma unroll
            for(int i=0;i<16;i++) a += sv1[h*16+i]*r[i];
            ae[h]=a;
        }
        ae2 = 0.f;
#pragma unroll
        for(int i=0;i<16;i++) ae2 += sv2[i]*r[i];
    } else {
        s = d = e - Ee;
#pragma unroll
        for(int h=0;h<4;h++) ae[h] = slae1[h];
        ae2 = slae2;
    }
    g_srcs[e]=s; g_dsts[e]=d; g_aedge2[e]=ae2;
    float4 av = __ldg((const float4*)&g_asrc1[s*4]);
    float4 dv = __ldg((const float4*)&g_adst1[d*4]);
    float al0 = lrelu(av.x + dv.x + ae[0]);
    float al1 = lrelu(av.y + dv.y + ae[1]);
    float al2 = lrelu(av.z + dv.z + ae[2]);
    float al3 = lrelu(av.w + dv.w + ae[3]);
    *(float4*)&g_alpha1[(size_t)e*4] = make_float4(al0,al1,al2,al3);
    atomicMax(&g_amax1[d*4+0], fkey(al0));
    atomicMax(&g_amax1[d*4+1], fkey(al1));
    atomicMax(&g_amax1[d*4+2], fkey(al2));
    atomicMax(&g_amax1[d*4+3], fkey(al3));
}

// ---------------- 6. exp + denom (layer1) ----------------
__global__ void k_ex1(){
    int e = blockIdx.x*blockDim.x + threadIdx.x;
    if(e >= EPt) return;
    int d = g_dsts[e];
    uint4 mk = *(const uint4*)&g_amax1[d*4];
    float4 al = *(const float4*)&g_alpha1[(size_t)e*4];
    float4 ex = make_float4(__expf(al.x - funkey(mk.x)),
                            __expf(al.y - funkey(mk.y)),
                            __expf(al.z - funkey(mk.z)),
                            __expf(al.w - funkey(mk.w)));
    *(float4*)&g_alpha1[(size_t)e*4] = ex;
    atomicAdd((float4*)&g_den1[d*4], ex);
}

// ---------------- 7. aggregate (layer1): warp per edge, 128ch ----------------
__global__ void k_agg1(){
    int lane = threadIdx.x & 31;
    long long w = ((long long)blockIdx.x*blockDim.x + threadIdx.x) >> 5;
    if(w >= EPt) return;
    int e = (int)w;
    int d = g_dsts[e], s = g_srcs[e];
    float4 ex  = *(const float4*)&g_alpha1[(size_t)e*4];
    float4 den = __ldg((const float4*)&g_den1[d*4]);
    float4 cf4 = make_float4(ex.x/(den.x+1e-16f), ex.y/(den.y+1e-16f),
                             ex.z/(den.z+1e-16f), ex.w/(den.w+1e-16f));
    int h = lane >> 3;
    float cf = (h==0)?cf4.x:(h==1)?cf4.y:(h==2)?cf4.z:cf4.w;
    float4 hv = __ldg((const float4*)&g_h1[(size_t)s*128 + lane*4]);
    float4 m = make_float4(hv.x*cf, hv.y*cf, hv.z*cf, hv.w*cf);
    atomicAdd((float4*)&g_out1[(size_t)d*128 + lane*4], m);
}

// ---------------- 8. per-node attention scalars, layer 2 ----------------
__global__ void k_a2(const float* __restrict__ as2, const float* __restrict__ ad2){
    int n = blockIdx.x*blockDim.x + threadIdx.x;
    if(n >= Nn) return;
    const float4* hp = (const float4*)&g_h2[(size_t)n*64];
    float s=0.f, d=0.f;
#pragma unroll
    for(int i=0;i<16;i++){
        float4 hv = hp[i];
        float4 sv = __ldg((const float4*)&as2[i*4]);
        float4 dv = __ldg((const float4*)&ad2[i*4]);
        s += hv.x*sv.x + hv.y*sv.y + hv.z*sv.z + hv.w*sv.w;
        d += hv.x*dv.x + hv.y*dv.y + hv.z*dv.z + hv.w*dv.w;
    }
    g_asrc2[n]=s; g_adst2[n]=d;
}

// ---------------- 9-10. alpha + exp/denom (layer2) ----------------
__global__ void k_alpha2(){
    int e = blockIdx.x*blockDim.x + threadIdx.x;
    if(e >= EPt) return;
    int s = g_srcs[e], d = g_dsts[e];
    float a = lrelu(g_asrc2[s] + g_adst2[d] + g_aedge2[e]);
    g_alpha2[e] = a;
    atomicMax(&g_amax2[d], fkey(a));
}
__global__ void k_ex2(){
    int e = blockIdx.x*blockDim.x + threadIdx.x;
    if(e >= EPt) return;
    int d = g_dsts[e];
    float ex = __expf(g_alpha2[e] - funkey(g_amax2[d]));
    g_alpha2[e] = ex;
    atomicAdd(&g_den2[d], ex);
}

// ---------------- 11. aggregate (layer2): 16 lanes per edge, 64ch ----------------
__global__ void k_agg2(){
    long long gt = (long long)blockIdx.x*blockDim.x + threadIdx.x;
    int lane = (int)(gt & 15);
    long long e64 = gt >> 4;
    if(e64 >= EPt) return;
    int e = (int)e64;
    int d = g_dsts[e], s = g_srcs[e];
    float cf = g_alpha2[e] / (__ldg(&g_den2[d]) + 1e-16f);
    float4 hv = __ldg((const float4*)&g_h2[(size_t)s*64 + lane*4]);
    float4 m = make_float4(hv.x*cf, hv.y*cf, hv.z*cf, hv.w*cf);
    atomicAdd((float4*)&g_out2[(size_t)d*64 + lane*4], m);
}

// ---------------- 12. bias + global mean pool ----------------
__global__ void k_pool(const int* __restrict__ batch, const float* __restrict__ b2){
    int idx = blockIdx.x*blockDim.x + threadIdx.x;
    if(idx >= Nn*16) return;
    int n = idx >> 4, c4 = idx & 15;
    int g = __ldg(&batch[n]);
    float4 v  = *(const float4*)&g_out2[(size_t)n*64 + c4*4];
    float4 bb = __ldg((const float4*)&b2[c4*4]);
    v.x += bb.x; v.y += bb.y; v.z += bb.z; v.w += bb.w;
    atomicAdd((float4*)&g_pool[g*64 + c4*4], v);
    if(c4 == 0) atomicAdd(&g_cnt[g], 1);
}
__global__ void k_final(float* __restrict__ out){
    int i = blockIdx.x*blockDim.x + threadIdx.x;
    if(i >= Gg*64) return;
    out[i] = g_pool[i] / fmaxf((float)g_cnt[i >> 6], 1.0f);
}

// ---------------- host launcher ----------------
extern "C" void kernel_launch(void* const* d_in, const int* in_sizes, int n_in,
                              void* d_out, int out_size){
    (void)in_sizes; (void)n_in; (void)out_size;
    const float* x     = (const float*)d_in[0];
    const int*   ei    = (const int*)d_in[1];     // int32 (JAX x64 disabled)
    const float* ea    = (const float*)d_in[2];
    const int*   batch = (const int*)d_in[3];     // int32
    const float* W1    = (const float*)d_in[4];
    const float* as1   = (const float*)d_in[5];
    const float* ad1   = (const float*)d_in[6];
    const float* We1   = (const float*)d_in[7];
    const float* ae1   = (const float*)d_in[8];
    const float* b1    = (const float*)d_in[9];
    const float* W2    = (const float*)d_in[10];
    const float* as2   = (const float*)d_in[11];
    const float* ad2   = (const float*)d_in[12];
    const float* We2   = (const float*)d_in[13];
    const float* ae2   = (const float*)d_in[14];
    const float* b2    = (const float*)d_in[15];
    float*       out   = (float*)d_out;

    void *p_amax1,*p_den1,*p_out1,*p_amax2,*p_den2,*p_out2,*p_sum,*p_pool,*p_cnt;
    void *p_h1,*p_h2;
    cudaGetSymbolAddress(&p_amax1, g_amax1);
    cudaGetSymbolAddress(&p_den1,  g_den1);
    cudaGetSymbolAddress(&p_out1,  g_out1);
    cudaGetSymbolAddress(&p_amax2, g_amax2);
    cudaGetSymbolAddress(&p_den2,  g_den2);
    cudaGetSymbolAddress(&p_out2,  g_out2);
    cudaGetSymbolAddress(&p_sum,   g_sum_ea);
    cudaGetSymbolAddress(&p_pool,  g_pool);
    cudaGetSymbolAddress(&p_cnt,   g_cnt);
    cudaGetSymbolAddress(&p_h1,    g_h1);
    cudaGetSymbolAddress(&p_h2,    g_h2);

    cudaMemsetAsync(p_amax1, 0, (size_t)Nn*4*sizeof(unsigned));
    cudaMemsetAsync(p_den1,  0, (size_t)Nn*4*sizeof(float));
    cudaMemsetAsync(p_out1,  0, (size_t)Nn*128*sizeof(float));
    cudaMemsetAsync(p_amax2, 0, (size_t)Nn*sizeof(unsigned));
    cudaMemsetAsync(p_den2,  0, (size_t)Nn*sizeof(float));
    cudaMemsetAsync(p_out2,  0, (size_t)Nn*64*sizeof(float));
    cudaMemsetAsync(p_sum,   0, 16*sizeof(float));
    cudaMemsetAsync(p_pool,  0, Gg*64*sizeof(float));
    cudaMemsetAsync(p_cnt,   0, Gg*sizeof(int));

    k_sum_ea<<<296, 256>>>(ea);
    k_setup<<<1, 64>>>(We1, ae1, We2, ae2);

    k_gemm<128,false><<<(Nn+63)/64, 256>>>(x, W1, nullptr, (float*)p_h1, Nn);
    k_a1<<<(Nn*4+255)/256, 256>>>(as1, ad1);
    k_alpha1<<<(EPt+255)/256, 256>>>(ei, ea);
    k_ex1<<<(EPt+255)/256, 256>>>();
    k_agg1<<<(int)(((long long)EPt*32 + 255)/256), 256>>>();

    k_gemm<64,true><<<(Nn+63)/64, 256>>>((float*)p_out1, W2, b1, (float*)p_h2, Nn);
    k_a2<<<(Nn+255)/256, 256>>>(as2, ad2);
    k_alpha2<<<(EPt+255)/256, 256>>>();
    k_ex2<<<(EPt+255)/256, 256>>>();
    k_agg2<<<(int)(((long long)EPt*16 + 255)/256), 256>>>();

    k_pool<<<(Nn*16+255)/256, 256>>>(batch, b2);
    k_final<<<(Gg*64+255)/256, 256>>>(out);
}

// round 3
// speedup vs baseline: 1.1762x; 1.1762x over previous
#include <cuda_runtime.h>
#include <math.h>

#define Nn   50000
#define Ee   800000
#define EPt  850000   // E + N self loops
#define Gg   64

// ---------------- scratch ----------------
__device__ __align__(16) float g_h1   [(size_t)Nn*128];
__device__ __align__(16) float g_out1 [(size_t)Nn*128];
__device__ __align__(16) float g_h2   [(size_t)Nn*64];
__device__ __align__(16) float g_asrc1[Nn*4];
__device__ __align__(16) float g_adst1[Nn*4];
__device__ __align__(16) float g_asrc2[Nn];
__device__ __align__(16) float g_adst2[Nn];
__device__ __align__(16) int   g_ssrc [EPt];        // sorted-by-dst src
__device__ __align__(16) float g_sae1 [(size_t)EPt*4]; // sorted a_edge layer1
__device__ __align__(16) float g_sae2 [EPt];        // sorted a_edge layer2
__device__ __align__(16) int   g_deg  [Nn];
__device__ __align__(16) int   g_off  [Nn+1];
__device__ __align__(16) int   g_cur  [Nn];
__device__ __align__(16) float g_sum_ea[16];
__device__ __align__(16) float g_v1[64];
__device__ __align__(16) float g_v2[16];
__device__ __align__(16) float g_lae1[4];
__device__ __align__(16) float g_lae2[1];
__device__ __align__(16) float g_pool[Gg*64];
__device__ __align__(16) int   g_cnt [Gg];

__device__ __forceinline__ float lrelu(float x){ return x > 0.f ? x : 0.2f*x; }

// ---------------- 1. sum of edge_attr rows + dst histogram ----------------
__global__ void k_sum_hist(const float* __restrict__ ea, const int* __restrict__ ei){
    float acc[16];
#pragma unroll
    for(int i=0;i<16;i++) acc[i]=0.f;
    int stride = gridDim.x*blockDim.x;
    for(int e = blockIdx.x*blockDim.x + threadIdx.x; e < EPt; e += stride){
        int d = (e < Ee) ? __ldg(&ei[Ee + e]) : (e - Ee);
        atomicAdd(&g_deg[d], 1);
        if(e < Ee){
            const float4* r = (const float4*)(ea + (size_t)e*16);
            float4 a=__ldg(r), b=__ldg(r+1), c=__ldg(r+2), dd=__ldg(r+3);
            acc[0]+=a.x; acc[1]+=a.y; acc[2]+=a.z; acc[3]+=a.w;
            acc[4]+=b.x; acc[5]+=b.y; acc[6]+=b.z; acc[7]+=b.w;
            acc[8]+=c.x; acc[9]+=c.y; acc[10]+=c.z; acc[11]+=c.w;
            acc[12]+=dd.x; acc[13]+=dd.y; acc[14]+=dd.z; acc[15]+=dd.w;
        }
    }
#pragma unroll
    for(int off=16; off; off>>=1)
#pragma unroll
        for(int i=0;i<16;i++) acc[i] += __shfl_xor_sync(0xffffffffu, acc[i], off);
    if((threadIdx.x & 31)==0)
#pragma unroll
        for(int i=0;i<16;i++) atomicAdd(&g_sum_ea[i], acc[i]);
}

// ---------------- 2. tiny setup: v1, v2, self-loop a_edge consts ----------------
__global__ void k_setup(const float* __restrict__ We1, const float* __restrict__ ae1,
                        const float* __restrict__ We2, const float* __restrict__ ae2){
    __shared__ float mean[16];
    int t = threadIdx.x;
    if(t < 16) mean[t] = g_sum_ea[t] * (1.0f/(float)Ee);
    {
        int h = t >> 4, d = t & 15;
        float s = 0.f;
        for(int c=0;c<32;c++) s += We1[d*128 + h*32 + c] * ae1[h*32 + c];
        g_v1[h*16 + d] = s;
    }
    if(t < 16){
        float s = 0.f;
        for(int c=0;c<64;c++) s += We2[t*64 + c] * ae2[c];
        g_v2[t] = s;
    }
    __syncthreads();
    if(t < 4){
        float s = 0.f;
        for(int d=0;d<16;d++) s += mean[d]*g_v1[t*16+d];
        g_lae1[t] = s;
    }
    if(t == 32){
        float s = 0.f;
        for(int d=0;d<16;d++) s += mean[d]*g_v2[d];
        g_lae2[0] = s;
    }
}

// ---------------- 3. exclusive scan of degrees (single block) ----------------
__global__ void k_scan(){
    __shared__ int tmp[1024];
    __shared__ int s_run;
    int t = threadIdx.x;
    if(t==0) s_run = 0;
    __syncthreads();
    for(int base=0; base<Nn; base+=1024){
        int i = base + t;
        int v = (i < Nn) ? g_deg[i] : 0;
        tmp[t] = v; __syncthreads();
#pragma unroll
        for(int off=1; off<1024; off<<=1){
            int add = (t>=off) ? tmp[t-off] : 0;
            __syncthreads();
            tmp[t] += add;
            __syncthreads();
        }
        int incl = tmp[t];
        int run = s_run;
        __syncthreads();
        if(i < Nn) g_off[i] = run + incl - v;
        if(t == 1023) s_run = run + incl;
        __syncthreads();
    }
    if(t==0) g_off[Nn] = EPt;
}

// ---------------- 4. scatter: compute a_edge + write sorted-by-dst arrays ----------------
__global__ void k_scatter(const int* __restrict__ ei, const float* __restrict__ ea){
    __shared__ float sv1[64], sv2[16], slae1[4], slae2;
    int t = threadIdx.x;
    if(t < 64) sv1[t] = g_v1[t];
    if(t < 16) sv2[t] = g_v2[t];
    if(t < 4)  slae1[t] = g_lae1[t];
    if(t == 0) slae2 = g_lae2[0];
    __syncthreads();
    int e = blockIdx.x*blockDim.x + t;
    if(e >= EPt) return;
    int s, d; float ae[4], ae2;
    if(e < Ee){
        s = __ldg(&ei[e]); d = __ldg(&ei[Ee + e]);
        float r[16];
        const float4* rp = (const float4*)(ea + (size_t)e*16);
        ((float4*)r)[0]=__ldg(rp); ((float4*)r)[1]=__ldg(rp+1);
        ((float4*)r)[2]=__ldg(rp+2); ((float4*)r)[3]=__ldg(rp+3);
#pragma unroll
        for(int h=0;h<4;h++){
            float a=0.f;
#pragma unroll
            for(int i=0;i<16;i++) a += sv1[h*16+i]*r[i];
            ae[h]=a;
        }
        ae2 = 0.f;
#pragma unroll
        for(int i=0;i<16;i++) ae2 += sv2[i]*r[i];
    } else {
        s = d = e - Ee;
#pragma unroll
        for(int h=0;h<4;h++) ae[h] = slae1[h];
        ae2 = slae2;
    }
    int pos = g_off[d] + atomicAdd(&g_cur[d], 1);
    g_ssrc[pos] = s;
    *(float4*)&g_sae1[(size_t)pos*4] = make_float4(ae[0],ae[1],ae[2],ae[3]);
    g_sae2[pos] = ae2;
}

// ---------------- 5. SGEMM (K=128) with fused a_src/a_dst epilogue ----------------
// C[M,NC] = act(A[M,128]) @ W[128,NC]; act = identity or elu(a+abias[k])
// epilogue: asrc[n(,h)] = sum_c C[n,c]*atts[c] (per head), same for attd
template<int NC, bool ELU>
__global__ __launch_bounds__(256) void k_gemm(const float* __restrict__ A,
                                              const float* __restrict__ W,
                                              const float* __restrict__ abias,
                                              const float* __restrict__ atts,
                                              const float* __restrict__ attd,
                                              float* __restrict__ C,
                                              float* __restrict__ oasrc,
                                              float* __restrict__ oadst, int M){
    constexpr int CPT = NC/16;
    __shared__ float As[64*36];
    __shared__ float Ws[32*NC];
    __shared__ float as_s[NC], ad_s[NC];
    const int t  = threadIdx.x;
    const int rg = t >> 4, cg = t & 15;
    const int r0 = blockIdx.x * 64;
    if(t < NC){ as_s[t]=__ldg(&atts[t]); ad_s[t]=__ldg(&attd[t]); }
    float acc[4][CPT];
#pragma unroll
    for(int i=0;i<4;i++)
#pragma unroll
        for(int j=0;j<CPT;j++) acc[i][j]=0.f;

    for(int kc=0; kc<128; kc+=32){
#pragma unroll
        for(int i=0;i<2;i++){
            int f = t + i*256; int r = f>>3; int c4 = f&7;
            float4 v = make_float4(0.f,0.f,0.f,0.f);
            if(r0 + r < M) v = __ldg((const float4*)&A[(size_t)(r0+r)*128 + kc + c4*4]);
            if(ELU){
                float4 bb = __ldg((const float4*)&abias[kc + c4*4]);
                v.x += bb.x; v.y += bb.y; v.z += bb.z; v.w += bb.w;
                v.x = v.x>0.f ? v.x : expm1f(v.x);
                v.y = v.y>0.f ? v.y : expm1f(v.y);
                v.z = v.z>0.f ? v.z : expm1f(v.z);
                v.w = v.w>0.f ? v.w : expm1f(v.w);
            }
            float* dst = &As[r*36 + c4*4];
            dst[0]=v.x; dst[1]=v.y; dst[2]=v.z; dst[3]=v.w;
        }
#pragma unroll
        for(int f=t; f < 32*NC/4; f += 256){
            int k = f/(NC/4); int c = f%(NC/4);
            *(float4*)&Ws[k*NC + c*4] = __ldg((const float4*)&W[(size_t)(kc+k)*NC + c*4]);
        }
        __syncthreads();
#pragma unroll 4
        for(int kk=0; kk<32; kk++){
            float a0 = As[(rg*4+0)*36+kk];
            float a1 = As[(rg*4+1)*36+kk];
            float a2 = As[(rg*4+2)*36+kk];
            float a3 = As[(rg*4+3)*36+kk];
            float4 b0 = *(const float4*)&Ws[kk*NC + cg*CPT];
            acc[0][0]+=a0*b0.x; acc[0][1]+=a0*b0.y; acc[0][2]+=a0*b0.z; acc[0][3]+=a0*b0.w;
            acc[1][0]+=a1*b0.x; acc[1][1]+=a1*b0.y; acc[1][2]+=a1*b0.z; acc[1][3]+=a1*b0.w;
            acc[2][0]+=a2*b0.x; acc[2][1]+=a2*b0.y; acc[2][2]+=a2*b0.z; acc[2][3]+=a2*b0.w;
            acc[3][0]+=a3*b0.x; acc[3][1]+=a3*b0.y; acc[3][2]+=a3*b0.z; acc[3][3]+=a3*b0.w;
            if constexpr (CPT == 8){
                float4 b1 = *(const float4*)&Ws[kk*NC + cg*CPT + 4];
                acc[0][4]+=a0*b1.x; acc[0][5]+=a0*b1.y; acc[0][6]+=a0*b1.z; acc[0][7]+=a0*b1.w;
                acc[1][4]+=a1*b1.x; acc[1][5]+=a1*b1.y; acc[1][6]+=a1*b1.z; acc[1][7]+=a1*b1.w;
                acc[2][4]+=a2*b1.x; acc[2][5]+=a2*b1.y; acc[2][6]+=a2*b1.z; acc[2][7]+=a2*b1.w;
                acc[3][4]+=a3*b1.x; acc[3][5]+=a3*b1.y; acc[3][6]+=a3*b1.z; acc[3][7]+=a3*b1.w;
            }
        }
        __syncthreads();
    }
#pragma unroll
    for(int i=0;i<4;i++){
        int row = r0 + rg*4 + i;
        float ps=0.f, pd=0.f;
#pragma unroll
        for(int j=0;j<CPT;j++){
            float a = acc[i][j];
            ps += a*as_s[cg*CPT+j]; pd += a*ad_s[cg*CPT+j];
        }
        if constexpr (NC == 128){
            // head = cg>>2; reduce across cg&3 (lane bits 0-1)
            ps += __shfl_xor_sync(0xffffffffu, ps, 1); pd += __shfl_xor_sync(0xffffffffu, pd, 1);
            ps += __shfl_xor_sync(0xffffffffu, ps, 2); pd += __shfl_xor_sync(0xffffffffu, pd, 2);
            if((cg&3)==0 && row<M){ oasrc[row*4+(cg>>2)]=ps; oadst[row*4+(cg>>2)]=pd; }
        } else {
            ps += __shfl_xor_sync(0xffffffffu, ps, 1); pd += __shfl_xor_sync(0xffffffffu, pd, 1);
            ps += __shfl_xor_sync(0xffffffffu, ps, 2); pd += __shfl_xor_sync(0xffffffffu, pd, 2);
            ps += __shfl_xor_sync(0xffffffffu, ps, 4); pd += __shfl_xor_sync(0xffffffffu, pd, 4);
            ps += __shfl_xor_sync(0xffffffffu, ps, 8); pd += __shfl_xor_sync(0xffffffffu, pd, 8);
            if(cg==0 && row<M){ oasrc[row]=ps; oadst[row]=pd; }
        }
        if(row < M){
#pragma unroll
            for(int j4=0; j4<CPT; j4+=4){
                float4 v = make_float4(acc[i][j4],acc[i][j4+1],acc[i][j4+2],acc[i][j4+3]);
                *(float4*)&C[(size_t)row*NC + cg*CPT + j4] = v;
            }
        }
    }
}

// ---------------- 6. fused layer-1: online softmax + aggregate (warp/node) ----------------
__global__ __launch_bounds__(256) void k_layer1(){
    int lane = threadIdx.x & 31;
    int d = (blockIdx.x*blockDim.x + threadIdx.x) >> 5;
    if(d >= Nn) return;
    int beg = g_off[d], end = g_off[d+1];
    int h = lane >> 3;
    float adst = __ldg(&g_adst1[d*4+h]);
    float m = -1e30f, sden = 0.f;
    float4 acc = make_float4(0.f,0.f,0.f,0.f);
    for(int i=beg; i<end; i++){
        int s = __ldg(&g_ssrc[i]);
        float asrc = __ldg(&g_asrc1[s*4+h]);
        float aee  = __ldg(&g_sae1[(size_t)i*4+h]);
        float a = lrelu(asrc + adst + aee);
        float mn = fmaxf(m, a);
        float sc = __expf(m - mn);
        float w  = __expf(a - mn);
        sden = sden*sc + w;
        float4 hv = __ldg((const float4*)&g_h1[(size_t)s*128 + lane*4]);
        acc.x = acc.x*sc + hv.x*w;
        acc.y = acc.y*sc + hv.y*w;
        acc.z = acc.z*sc + hv.z*w;
        acc.w = acc.w*sc + hv.w*w;
        m = mn;
    }
    float inv = 1.f/(sden + 1e-16f);
    *(float4*)&g_out1[(size_t)d*128 + lane*4] =
        make_float4(acc.x*inv, acc.y*inv, acc.z*inv, acc.w*inv);
}

// ---------------- 7. fused layer-2 + pool (warp/node, float2 lanes) ----------------
__global__ __launch_bounds__(256) void k_layer2(const int* __restrict__ batch){
    int lane = threadIdx.x & 31;
    int d = (blockIdx.x*blockDim.x + threadIdx.x) >> 5;
    if(d >= Nn) return;
    int beg = g_off[d], end = g_off[d+1];
    float adst = __ldg(&g_adst2[d]);
    float m = -1e30f, sden = 0.f;
    float2 acc = make_float2(0.f,0.f);
    for(int i=beg; i<end; i++){
        int s = __ldg(&g_ssrc[i]);
        float a = lrelu(__ldg(&g_asrc2[s]) + adst + __ldg(&g_sae2[i]));
        float mn = fmaxf(m, a);
        float sc = __expf(m - mn);
        float w  = __expf(a - mn);
        sden = sden*sc + w;
        float2 hv = __ldg((const float2*)&g_h2[(size_t)s*64 + lane*2]);
        acc.x = acc.x*sc + hv.x*w;
        acc.y = acc.y*sc + hv.y*w;
        m = mn;
    }
    float inv = 1.f/(sden + 1e-16f);
    int g = __ldg(&batch[d]);
    atomicAdd((float2*)&g_pool[g*64 + lane*2], make_float2(acc.x*inv, acc.y*inv));
    if(lane==0) atomicAdd(&g_cnt[g], 1);
}

// ---------------- 8. final: mean + bias ----------------
__global__ void k_final(float* __restrict__ out, const float* __restrict__ b2){
    int i = blockIdx.x*blockDim.x + threadIdx.x;
    if(i >= Gg*64) return;
    out[i] = g_pool[i] / fmaxf((float)g_cnt[i >> 6], 1.0f) + __ldg(&b2[i & 63]);
}

// ---------------- host launcher ----------------
extern "C" void kernel_launch(void* const* d_in, const int* in_sizes, int n_in,
                              void* d_out, int out_size){
    (void)in_sizes; (void)n_in; (void)out_size;
    const float* x     = (const float*)d_in[0];
    const int*   ei    = (const int*)d_in[1];
    const float* ea    = (const float*)d_in[2];
    const int*   batch = (const int*)d_in[3];
    const float* W1    = (const float*)d_in[4];
    const float* as1   = (const float*)d_in[5];
    const float* ad1   = (const float*)d_in[6];
    const float* We1   = (const float*)d_in[7];
    const float* ae1   = (const float*)d_in[8];
    const float* b1    = (const float*)d_in[9];
    const float* W2    = (const float*)d_in[10];
    const float* as2   = (const float*)d_in[11];
    const float* ad2   = (const float*)d_in[12];
    const float* We2   = (const float*)d_in[13];
    const float* ae2   = (const float*)d_in[14];
    const float* b2    = (const float*)d_in[15];
    float*       out   = (float*)d_out;

    void *p_deg,*p_cur,*p_sum,*p_pool,*p_cnt,*p_h1,*p_out1,*p_h2;
    void *p_asrc1,*p_adst1,*p_asrc2,*p_adst2;
    cudaGetSymbolAddress(&p_deg,  g_deg);
    cudaGetSymbolAddress(&p_cur,  g_cur);
    cudaGetSymbolAddress(&p_sum,  g_sum_ea);
    cudaGetSymbolAddress(&p_pool, g_pool);
    cudaGetSymbolAddress(&p_cnt,  g_cnt);
    cudaGetSymbolAddress(&p_h1,   g_h1);
    cudaGetSymbolAddress(&p_out1, g_out1);
    cudaGetSymbolAddress(&p_h2,   g_h2);
    cudaGetSymbolAddress(&p_asrc1, g_asrc1);
    cudaGetSymbolAddress(&p_adst1, g_adst1);
    cudaGetSymbolAddress(&p_asrc2, g_asrc2);
    cudaGetSymbolAddress(&p_adst2, g_adst2);

    cudaMemsetAsync(p_deg, 0, Nn*sizeof(int));
    cudaMemsetAsync(p_cur, 0, Nn*sizeof(int));
    cudaMemsetAsync(p_sum, 0, 16*sizeof(float));
    cudaMemsetAsync(p_pool,0, Gg*64*sizeof(float));
    cudaMemsetAsync(p_cnt, 0, Gg*sizeof(int));

    k_sum_hist<<<592, 256>>>(ea, ei);
    k_setup<<<1, 64>>>(We1, ae1, We2, ae2);
    k_scan<<<1, 1024>>>();
    k_scatter<<<(EPt+255)/256, 256>>>(ei, ea);

    k_gemm<128,false><<<(Nn+63)/64, 256>>>(x, W1, nullptr, as1, ad1,
                                           (float*)p_h1, (float*)p_asrc1, (float*)p_adst1, Nn);
    k_layer1<<<(Nn*32+255)/256, 256>>>();

    k_gemm<64,true><<<(Nn+63)/64, 256>>>((float*)p_out1, W2, b1, as2, ad2,
                                         (float*)p_h2, (float*)p_asrc2, (float*)p_adst2, Nn);
    k_layer2<<<(Nn*32+255)/256, 256>>>(batch);

    k_final<<<(Gg*64+255)/256, 256>>>(out, b2);
}

// round 4
// speedup vs baseline: 1.3887x; 1.1806x over previous
#include <cuda_runtime.h>
#include <math.h>

#define Nn   50000
#define Ee   800000
#define EPt  850000   // E + N self loops
#define Gg   64
#define NBLK 49       // ceil(Nn/1024)

// ---------------- scratch ----------------
__device__ __align__(16) float g_h1   [(size_t)Nn*128];
__device__ __align__(16) float g_out1 [(size_t)Nn*128];
__device__ __align__(16) float g_h2   [(size_t)Nn*64];
__device__ __align__(16) float g_asrc1[Nn*4];
__device__ __align__(16) float g_adst1[Nn*4];
__device__ __align__(16) float g_asrc2[Nn];
__device__ __align__(16) float g_adst2[Nn];
__device__ __align__(16) float g_tae1 [(size_t)Ee*4];  // unsorted a_edge L1
__device__ __align__(16) float g_tae2 [Ee];            // unsorted a_edge L2
__device__ __align__(16) int   g_ssrc [EPt];           // sorted-by-dst src
__device__ __align__(16) float g_sae1 [(size_t)EPt*4]; // sorted a_edge L1
__device__ __align__(16) float g_sae2 [EPt];           // sorted a_edge L2
__device__ __align__(16) int   g_deg  [Nn];
__device__ __align__(16) int   g_off  [Nn+1];
__device__ __align__(16) int   g_cur  [Nn];
__device__ __align__(16) int   g_bsum [NBLK];
__device__ __align__(16) int   g_boff [NBLK];
__device__ __align__(16) float g_sum_ea[16];
__device__ __align__(16) float g_v1[64];
__device__ __align__(16) float g_v2[16];
__device__ __align__(16) float g_lae1[4];
__device__ __align__(16) float g_lae2[1];
__device__ __align__(16) float g_pool[Gg*64];
__device__ __align__(16) int   g_cnt [Gg];

__device__ __forceinline__ float lrelu(float x){ return x > 0.f ? x : 0.2f*x; }

// ---------------- 1. v1/v2 from weights only ----------------
__global__ void k_v(const float* __restrict__ We1, const float* __restrict__ ae1,
                    const float* __restrict__ We2, const float* __restrict__ ae2){
    int t = threadIdx.x;
    {
        int h = t >> 4, d = t & 15;
        float s = 0.f;
        for(int c=0;c<32;c++) s += We1[d*128 + h*32 + c] * ae1[h*32 + c];
        g_v1[h*16 + d] = s;
    }
    if(t < 16){
        float s = 0.f;
        for(int c=0;c<64;c++) s += We2[t*64 + c] * ae2[c];
        g_v2[t] = s;
    }
}

// ---------------- 2. pass1: hist + sum_ea + a_edge dots into temp ----------------
__global__ void k_pass1(const float* __restrict__ ea, const int* __restrict__ ei){
    __shared__ float sv1[64], sv2[16];
    int t = threadIdx.x;
    if(t < 64) sv1[t] = g_v1[t];
    if(t < 16) sv2[t] = g_v2[t];
    __syncthreads();
    float acc[16];
#pragma unroll
    for(int i=0;i<16;i++) acc[i]=0.f;
    int stride = gridDim.x*blockDim.x;
    for(int e = blockIdx.x*blockDim.x + t; e < EPt; e += stride){
        int d = (e < Ee) ? __ldg(&ei[Ee + e]) : (e - Ee);
        atomicAdd(&g_deg[d], 1);
        if(e < Ee){
            float r[16];
            const float4* rp = (const float4*)(ea + (size_t)e*16);
            ((float4*)r)[0]=__ldg(rp);   ((float4*)r)[1]=__ldg(rp+1);
            ((float4*)r)[2]=__ldg(rp+2); ((float4*)r)[3]=__ldg(rp+3);
#pragma unroll
            for(int i=0;i<16;i++) acc[i] += r[i];
            float ae[4];
#pragma unroll
            for(int h=0;h<4;h++){
                float a=0.f;
#pragma unroll
                for(int i=0;i<16;i++) a += sv1[h*16+i]*r[i];
                ae[h]=a;
            }
            float a2=0.f;
#pragma unroll
            for(int i=0;i<16;i++) a2 += sv2[i]*r[i];
            *(float4*)&g_tae1[(size_t)e*4] = make_float4(ae[0],ae[1],ae[2],ae[3]);
            g_tae2[e] = a2;
        }
    }
#pragma unroll
    for(int off=16; off; off>>=1)
#pragma unroll
        for(int i=0;i<16;i++) acc[i] += __shfl_xor_sync(0xffffffffu, acc[i], off);
    if((t & 31)==0)
#pragma unroll
        for(int i=0;i<16;i++) atomicAdd(&g_sum_ea[i], acc[i]);
}

// ---------------- 3. lae constants from mean ----------------
__global__ void k_lae(){
    int t = threadIdx.x;
    if(t < 4){
        float s = 0.f;
        for(int d=0;d<16;d++) s += (g_sum_ea[d]*(1.0f/(float)Ee))*g_v1[t*16+d];
        g_lae1[t] = s;
    }
    if(t == 4){
        float s = 0.f;
        for(int d=0;d<16;d++) s += (g_sum_ea[d]*(1.0f/(float)Ee))*g_v2[d];
        g_lae2[0] = s;
    }
}

// ---------------- 4. scan (3 kernels, warp-shuffle) ----------------
__global__ void k_scanA(){
    __shared__ int wsum[8], wexc[8];
    int t = threadIdx.x, blk = blockIdx.x;
    int base = blk*1024 + t*4;
    int v0 = (base+0<Nn)?g_deg[base+0]:0;
    int v1 = (base+1<Nn)?g_deg[base+1]:0;
    int v2 = (base+2<Nn)?g_deg[base+2]:0;
    int v3 = (base+3<Nn)?g_deg[base+3]:0;
    int s = v0+v1+v2+v3;
    int lane = t&31, w = t>>5;
    int ps = s;
#pragma unroll
    for(int off=1; off<32; off<<=1){
        int n = __shfl_up_sync(0xffffffffu, ps, off);
        if(lane>=off) ps += n;
    }
    if(lane==31) wsum[w] = ps;
    __syncthreads();
    if(t==0){
        int r=0;
#pragma unroll
        for(int k=0;k<8;k++){ wexc[k]=r; r+=wsum[k]; }
        g_bsum[blk]=r;
    }
    __syncthreads();
    int run = wexc[w] + ps - s;
    if(base+0<Nn) g_off[base+0]=run; run+=v0;
    if(base+1<Nn) g_off[base+1]=run; run+=v1;
    if(base+2<Nn) g_off[base+2]=run; run+=v2;
    if(base+3<Nn) g_off[base+3]=run;
}
__global__ void k_scanB(){
    if(threadIdx.x==0){
        int r=0;
        for(int b=0;b<NBLK;b++){ g_boff[b]=r; r+=g_bsum[b]; }
        g_off[Nn]=EPt;
    }
}
__global__ void k_scanC(){
    int blk = blockIdx.x;
    if(blk==0) return;
    int add = g_boff[blk];
    int base = blk*1024 + threadIdx.x*4;
#pragma unroll
    for(int j=0;j<4;j++)
        if(base+j < Nn) g_off[base+j] += add;
}

// ---------------- 5. scatter (pure permute) ----------------
__global__ void k_scatter(const int* __restrict__ ei){
    int e = blockIdx.x*blockDim.x + threadIdx.x;
    if(e >= EPt) return;
    int s, d; float4 ae; float ae2;
    if(e < Ee){
        s = __ldg(&ei[e]); d = __ldg(&ei[Ee + e]);
        ae = *(const float4*)&g_tae1[(size_t)e*4];
        ae2 = g_tae2[e];
    } else {
        s = d = e - Ee;
        ae = make_float4(g_lae1[0],g_lae1[1],g_lae1[2],g_lae1[3]);
        ae2 = g_lae2[0];
    }
    int pos = g_off[d] + atomicAdd(&g_cur[d], 1);
    g_ssrc[pos] = s;
    *(float4*)&g_sae1[(size_t)pos*4] = ae;
    g_sae2[pos] = ae2;
}

// ---------------- 6. SGEMM (K=128) with fused a_src/a_dst epilogue ----------------
template<int NC, bool ELU>
__global__ __launch_bounds__(256) void k_gemm(const float* __restrict__ A,
                                              const float* __restrict__ W,
                                              const float* __restrict__ abias,
                                              const float* __restrict__ atts,
                                              const float* __restrict__ attd,
                                              float* __restrict__ C,
                                              float* __restrict__ oasrc,
                                              float* __restrict__ oadst, int M){
    constexpr int CPT = NC/16;
    __shared__ float As[64*36];
    __shared__ float Ws[32*NC];
    __shared__ float as_s[NC], ad_s[NC];
    const int t  = threadIdx.x;
    const int rg = t >> 4, cg = t & 15;
    const int r0 = blockIdx.x * 64;
    if(t < NC){ as_s[t]=__ldg(&atts[t]); ad_s[t]=__ldg(&attd[t]); }
    float acc[4][CPT];
#pragma unroll
    for(int i=0;i<4;i++)
#pragma unroll
        for(int j=0;j<CPT;j++) acc[i][j]=0.f;

    for(int kc=0; kc<128; kc+=32){
#pragma unroll
        for(int i=0;i<2;i++){
            int f = t + i*256; int r = f>>3; int c4 = f&7;
            float4 v = make_float4(0.f,0.f,0.f,0.f);
            if(r0 + r < M) v = __ldg((const float4*)&A[(size_t)(r0+r)*128 + kc + c4*4]);
            if(ELU){
                float4 bb = __ldg((const float4*)&abias[kc + c4*4]);
                v.x += bb.x; v.y += bb.y; v.z += bb.z; v.w += bb.w;
                v.x = v.x>0.f ? v.x : expm1f(v.x);
                v.y = v.y>0.f ? v.y : expm1f(v.y);
                v.z = v.z>0.f ? v.z : expm1f(v.z);
                v.w = v.w>0.f ? v.w : expm1f(v.w);
            }
            float* dst = &As[r*36 + c4*4];
            dst[0]=v.x; dst[1]=v.y; dst[2]=v.z; dst[3]=v.w;
        }
#pragma unroll
        for(int f=t; f < 32*NC/4; f += 256){
            int k = f/(NC/4); int c = f%(NC/4);
            *(float4*)&Ws[k*NC + c*4] = __ldg((const float4*)&W[(size_t)(kc+k)*NC + c*4]);
        }
        __syncthreads();
#pragma unroll 4
        for(int kk=0; kk<32; kk++){
            float a0 = As[(rg*4+0)*36+kk];
            float a1 = As[(rg*4+1)*36+kk];
            float a2 = As[(rg*4+2)*36+kk];
            float a3 = As[(rg*4+3)*36+kk];
            float4 b0 = *(const float4*)&Ws[kk*NC + cg*CPT];
            acc[0][0]+=a0*b0.x; acc[0][1]+=a0*b0.y; acc[0][2]+=a0*b0.z; acc[0][3]+=a0*b0.w;
            acc[1][0]+=a1*b0.x; acc[1][1]+=a1*b0.y; acc[1][2]+=a1*b0.z; acc[1][3]+=a1*b0.w;
            acc[2][0]+=a2*b0.x; acc[2][1]+=a2*b0.y; acc[2][2]+=a2*b0.z; acc[2][3]+=a2*b0.w;
            acc[3][0]+=a3*b0.x; acc[3][1]+=a3*b0.y; acc[3][2]+=a3*b0.z; acc[3][3]+=a3*b0.w;
            if constexpr (CPT == 8){
                float4 b1 = *(const float4*)&Ws[kk*NC + cg*CPT + 4];
                acc[0][4]+=a0*b1.x; acc[0][5]+=a0*b1.y; acc[0][6]+=a0*b1.z; acc[0][7]+=a0*b1.w;
                acc[1][4]+=a1*b1.x; acc[1][5]+=a1*b1.y; acc[1][6]+=a1*b1.z; acc[1][7]+=a1*b1.w;
                acc[2][4]+=a2*b1.x; acc[2][5]+=a2*b1.y; acc[2][6]+=a2*b1.z; acc[2][7]+=a2*b1.w;
                acc[3][4]+=a3*b1.x; acc[3][5]+=a3*b1.y; acc[3][6]+=a3*b1.z; acc[3][7]+=a3*b1.w;
            }
        }
        __syncthreads();
    }
#pragma unroll
    for(int i=0;i<4;i++){
        int row = r0 + rg*4 + i;
        float ps=0.f, pd=0.f;
#pragma unroll
        for(int j=0;j<CPT;j++){
            float a = acc[i][j];
            ps += a*as_s[cg*CPT+j]; pd += a*ad_s[cg*CPT+j];
        }
        if constexpr (NC == 128){
            ps += __shfl_xor_sync(0xffffffffu, ps, 1); pd += __shfl_xor_sync(0xffffffffu, pd, 1);
            ps += __shfl_xor_sync(0xffffffffu, ps, 2); pd += __shfl_xor_sync(0xffffffffu, pd, 2);
            if((cg&3)==0 && row<M){ oasrc[row*4+(cg>>2)]=ps; oadst[row*4+(cg>>2)]=pd; }
        } else {
            ps += __shfl_xor_sync(0xffffffffu, ps, 1); pd += __shfl_xor_sync(0xffffffffu, pd, 1);
            ps += __shfl_xor_sync(0xffffffffu, ps, 2); pd += __shfl_xor_sync(0xffffffffu, pd, 2);
            ps += __shfl_xor_sync(0xffffffffu, ps, 4); pd += __shfl_xor_sync(0xffffffffu, pd, 4);
            ps += __shfl_xor_sync(0xffffffffu, ps, 8); pd += __shfl_xor_sync(0xffffffffu, pd, 8);
            if(cg==0 && row<M){ oasrc[row]=ps; oadst[row]=pd; }
        }
        if(row < M){
#pragma unroll
            for(int j4=0; j4<CPT; j4+=4){
                float4 v = make_float4(acc[i][j4],acc[i][j4+1],acc[i][j4+2],acc[i][j4+3]);
                *(float4*)&C[(size_t)row*NC + cg*CPT + j4] = v;
            }
        }
    }
}

// ---------------- 7. fused layer-1: online softmax + aggregate (warp/node, x4 unroll) ----------------
#define COMB1(a, hv) { \
    if((a) <= m){ float w=__expf((a)-m); sden+=w; \
        acc.x+=hv.x*w; acc.y+=hv.y*w; acc.z+=hv.z*w; acc.w+=hv.w*w; } \
    else { float sc=__expf(m-(a)); sden=sden*sc+1.f; \
        acc.x=acc.x*sc+hv.x; acc.y=acc.y*sc+hv.y; acc.z=acc.z*sc+hv.z; acc.w=acc.w*sc+hv.w; m=(a);} }

__global__ __launch_bounds__(256) void k_layer1(){
    int lane = threadIdx.x & 31;
    int d = (blockIdx.x*blockDim.x + threadIdx.x) >> 5;
    if(d >= Nn) return;
    int beg = g_off[d], end = g_off[d+1];
    int h = lane >> 3;
    float adst = __ldg(&g_adst1[d*4+h]);
    float m = -1e30f, sden = 0.f;
    float4 acc = make_float4(0.f,0.f,0.f,0.f);
    int i = beg;
    for(; i+4 <= end; i+=4){
        int s0=__ldg(&g_ssrc[i+0]), s1=__ldg(&g_ssrc[i+1]),
            s2=__ldg(&g_ssrc[i+2]), s3=__ldg(&g_ssrc[i+3]);
        float e0=__ldg(&g_sae1[(size_t)(i+0)*4+h]), e1=__ldg(&g_sae1[(size_t)(i+1)*4+h]),
              e2=__ldg(&g_sae1[(size_t)(i+2)*4+h]), e3=__ldg(&g_sae1[(size_t)(i+3)*4+h]);
        float a0=lrelu(__ldg(&g_asrc1[s0*4+h])+adst+e0);
        float a1=lrelu(__ldg(&g_asrc1[s1*4+h])+adst+e1);
        float a2=lrelu(__ldg(&g_asrc1[s2*4+h])+adst+e2);
        float a3=lrelu(__ldg(&g_asrc1[s3*4+h])+adst+e3);
        float4 v0=__ldg((const float4*)&g_h1[(size_t)s0*128+lane*4]);
        float4 v1=__ldg((const float4*)&g_h1[(size_t)s1*128+lane*4]);
        float4 v2=__ldg((const float4*)&g_h1[(size_t)s2*128+lane*4]);
        float4 v3=__ldg((const float4*)&g_h1[(size_t)s3*128+lane*4]);
        COMB1(a0,v0); COMB1(a1,v1); COMB1(a2,v2); COMB1(a3,v3);
    }
    for(; i<end; i++){
        int s = __ldg(&g_ssrc[i]);
        float a = lrelu(__ldg(&g_asrc1[s*4+h])+adst+__ldg(&g_sae1[(size_t)i*4+h]));
        float4 hv = __ldg((const float4*)&g_h1[(size_t)s*128+lane*4]);
        COMB1(a,hv);
    }
    float inv = 1.f/sden;
    *(float4*)&g_out1[(size_t)d*128 + lane*4] =
        make_float4(acc.x*inv, acc.y*inv, acc.z*inv, acc.w*inv);
}

// ---------------- 8. fused layer-2 + pool (warp/node, float2, x4 unroll) ----------------
#define COMB2(a, hv) { \
    if((a) <= m){ float w=__expf((a)-m); sden+=w; acc.x+=hv.x*w; acc.y+=hv.y*w; } \
    else { float sc=__expf(m-(a)); sden=sden*sc+1.f; \
        acc.x=acc.x*sc+hv.x; acc.y=acc.y*sc+hv.y; m=(a);} }

__global__ __launch_bounds__(256) void k_layer2(const int* __restrict__ batch){
    int lane = threadIdx.x & 31;
    int d = (blockIdx.x*blockDim.x + threadIdx.x) >> 5;
    if(d >= Nn) return;
    int beg = g_off[d], end = g_off[d+1];
    float adst = __ldg(&g_adst2[d]);
    float m = -1e30f, sden = 0.f;
    float2 acc = make_float2(0.f,0.f);
    int i = beg;
    for(; i+4 <= end; i+=4){
        int s0=__ldg(&g_ssrc[i+0]), s1=__ldg(&g_ssrc[i+1]),
            s2=__ldg(&g_ssrc[i+2]), s3=__ldg(&g_ssrc[i+3]);
        float a0=lrelu(__ldg(&g_asrc2[s0])+adst+__ldg(&g_sae2[i+0]));
        float a1=lrelu(__ldg(&g_asrc2[s1])+adst+__ldg(&g_sae2[i+1]));
        float a2=lrelu(__ldg(&g_asrc2[s2])+adst+__ldg(&g_sae2[i+2]));
        float a3=lrelu(__ldg(&g_asrc2[s3])+adst+__ldg(&g_sae2[i+3]));
        float2 v0=__ldg((const float2*)&g_h2[(size_t)s0*64+lane*2]);
        float2 v1=__ldg((const float2*)&g_h2[(size_t)s1*64+lane*2]);
        float2 v2=__ldg((const float2*)&g_h2[(size_t)s2*64+lane*2]);
        float2 v3=__ldg((const float2*)&g_h2[(size_t)s3*64+lane*2]);
        COMB2(a0,v0); COMB2(a1,v1); COMB2(a2,v2); COMB2(a3,v3);
    }
    for(; i<end; i++){
        int s = __ldg(&g_ssrc[i]);
        float a = lrelu(__ldg(&g_asrc2[s])+adst+__ldg(&g_sae2[i]));
        float2 hv = __ldg((const float2*)&g_h2[(size_t)s*64+lane*2]);
        COMB2(a,hv);
    }
    float inv = 1.f/sden;
    int g = __ldg(&batch[d]);
    atomicAdd((float2*)&g_pool[g*64 + lane*2], make_float2(acc.x*inv, acc.y*inv));
    if(lane==0) atomicAdd(&g_cnt[g], 1);
}

// ---------------- 9. final: mean + bias ----------------
__global__ void k_final(float* __restrict__ out, const float* __restrict__ b2){
    int i = blockIdx.x*blockDim.x + threadIdx.x;
    if(i >= Gg*64) return;
    out[i] = g_pool[i] / fmaxf((float)g_cnt[i >> 6], 1.0f) + __ldg(&b2[i & 63]);
}

// ---------------- host launcher ----------------
extern "C" void kernel_launch(void* const* d_in, const int* in_sizes, int n_in,
                              void* d_out, int out_size){
    (void)in_sizes; (void)n_in; (void)out_size;
    const float* x     = (const float*)d_in[0];
    const int*   ei    = (const int*)d_in[1];
    const float* ea    = (const float*)d_in[2];
    const int*   batch = (const int*)d_in[3];
    const float* W1    = (const float*)d_in[4];
    const float* as1   = (const float*)d_in[5];
    const float* ad1   = (const float*)d_in[6];
    const float* We1   = (const float*)d_in[7];
    const float* ae1   = (const float*)d_in[8];
    const float* b1    = (const float*)d_in[9];
    const float* W2    = (const float*)d_in[10];
    const float* as2   = (const float*)d_in[11];
    const float* ad2   = (const float*)d_in[12];
    const float* We2   = (const float*)d_in[13];
    const float* ae2   = (const float*)d_in[14];
    const float* b2    = (const float*)d_in[15];
    float*       out   = (float*)d_out;

    void *p_deg,*p_cur,*p_sum,*p_pool,*p_cnt,*p_h1,*p_out1,*p_h2;
    void *p_asrc1,*p_adst1,*p_asrc2,*p_adst2;
    cudaGetSymbolAddress(&p_deg,  g_deg);
    cudaGetSymbolAddress(&p_cur,  g_cur);
    cudaGetSymbolAddress(&p_sum,  g_sum_ea);
    cudaGetSymbolAddress(&p_pool, g_pool);
    cudaGetSymbolAddress(&p_cnt,  g_cnt);
    cudaGetSymbolAddress(&p_h1,   g_h1);
    cudaGetSymbolAddress(&p_out1, g_out1);
    cudaGetSymbolAddress(&p_h2,   g_h2);
    cudaGetSymbolAddress(&p_asrc1, g_asrc1);
    cudaGetSymbolAddress(&p_adst1, g_adst1);
    cudaGetSymbolAddress(&p_asrc2, g_asrc2);
    cudaGetSymbolAddress(&p_adst2, g_adst2);

    cudaMemsetAsync(p_deg, 0, Nn*sizeof(int));
    cudaMemsetAsync(p_cur, 0, Nn*sizeof(int));
    cudaMemsetAsync(p_sum, 0, 16*sizeof(float));
    cudaMemsetAsync(p_pool,0, Gg*64*sizeof(float));
    cudaMemsetAsync(p_cnt, 0, Gg*sizeof(int));

    k_v<<<1, 64>>>(We1, ae1, We2, ae2);
    k_pass1<<<592, 256>>>(ea, ei);
    k_lae<<<1, 32>>>();
    k_scanA<<<NBLK, 256>>>();
    k_scanB<<<1, 32>>>();
    k_scanC<<<NBLK, 256>>>();
    k_scatter<<<(EPt+255)/256, 256>>>(ei);

    k_gemm<128,false><<<(Nn+63)/64, 256>>>(x, W1, nullptr, as1, ad1,
                                           (float*)p_h1, (float*)p_asrc1, (float*)p_adst1, Nn);
    k_layer1<<<(Nn*32+255)/256, 256>>>();

    k_gemm<64,true><<<(Nn+63)/64, 256>>>((float*)p_out1, W2, b1, as2, ad2,
                                         (float*)p_h2, (float*)p_asrc2, (float*)p_adst2, Nn);
    k_layer2<<<(Nn*32+255)/256, 256>>>(batch);

    k_final<<<(Gg*64+255)/256, 256>>>(out, b2);
}

// round 5
// speedup vs baseline: 1.4543x; 1.0472x over previous
#include <cuda_runtime.h>
#include <math.h>

#define Nn   50000
#define Ee   800000
#define EPt  850000   // E + N self loops
#define Gg   64
#define NBLK 49       // ceil(Nn/1024)

// ---------------- scratch ----------------
__device__ __align__(16) float g_h1   [(size_t)Nn*128];
__device__ __align__(16) float g_out1 [(size_t)Nn*128];
__device__ __align__(16) float g_h2   [(size_t)Nn*64];
__device__ __align__(16) float g_asrc1[Nn*4];
__device__ __align__(16) float g_adst1[Nn*4];
__device__ __align__(16) float g_asrc2[Nn];
__device__ __align__(16) float g_adst2[Nn];
__device__ __align__(16) float g_tae1 [(size_t)Ee*4];  // unsorted a_edge L1
__device__ __align__(16) float g_tae2 [Ee];            // unsorted a_edge L2
__device__ __align__(16) int   g_ssrc [EPt];           // sorted-by-dst src
__device__ __align__(16) float g_sae1 [(size_t)EPt*4]; // sorted a_edge L1
__device__ __align__(16) float g_sae2 [EPt];           // sorted a_edge L2
__device__ __align__(16) int   g_deg  [Nn];
__device__ __align__(16) int   g_off  [Nn+1];
__device__ __align__(16) int   g_cur  [Nn];
__device__ __align__(16) int   g_bsum [NBLK];
__device__ __align__(16) int   g_boff [NBLK];
__device__ __align__(16) float g_sum_ea[16];
__device__ __align__(16) float g_v1[64];
__device__ __align__(16) float g_v2[16];
__device__ __align__(16) float g_lae1[4];
__device__ __align__(16) float g_lae2[1];
__device__ __align__(16) float g_pool[Gg*64];
__device__ __align__(16) int   g_cnt [Gg];

__device__ __forceinline__ float lrelu(float x){ return x > 0.f ? x : 0.2f*x; }

// ---------------- 1. v1/v2 from weights only ----------------
__global__ void k_v(const float* __restrict__ We1, const float* __restrict__ ae1,
                    const float* __restrict__ We2, const float* __restrict__ ae2){
    int t = threadIdx.x;
    {
        int h = t >> 4, d = t & 15;
        float s = 0.f;
        for(int c=0;c<32;c++) s += We1[d*128 + h*32 + c] * ae1[h*32 + c];
        g_v1[h*16 + d] = s;
    }
    if(t < 16){
        float s = 0.f;
        for(int c=0;c<64;c++) s += We2[t*64 + c] * ae2[c];
        g_v2[t] = s;
    }
}

// ---------------- 2. pass1: hist + sum_ea + a_edge dots into temp ----------------
__global__ void k_pass1(const float* __restrict__ ea, const int* __restrict__ ei){
    __shared__ float sv1[64], sv2[16];
    int t = threadIdx.x;
    if(t < 64) sv1[t] = g_v1[t];
    if(t < 16) sv2[t] = g_v2[t];
    __syncthreads();
    float acc[16];
#pragma unroll
    for(int i=0;i<16;i++) acc[i]=0.f;
    int stride = gridDim.x*blockDim.x;
    for(int e = blockIdx.x*blockDim.x + t; e < EPt; e += stride){
        int d = (e < Ee) ? __ldg(&ei[Ee + e]) : (e - Ee);
        atomicAdd(&g_deg[d], 1);
        if(e < Ee){
            float r[16];
            const float4* rp = (const float4*)(ea + (size_t)e*16);
            ((float4*)r)[0]=__ldg(rp);   ((float4*)r)[1]=__ldg(rp+1);
            ((float4*)r)[2]=__ldg(rp+2); ((float4*)r)[3]=__ldg(rp+3);
#pragma unroll
            for(int i=0;i<16;i++) acc[i] += r[i];
            float ae[4];
#pragma unroll
            for(int h=0;h<4;h++){
                float a=0.f;
#pragma unroll
                for(int i=0;i<16;i++) a += sv1[h*16+i]*r[i];
                ae[h]=a;
            }
            float a2=0.f;
#pragma unroll
            for(int i=0;i<16;i++) a2 += sv2[i]*r[i];
            *(float4*)&g_tae1[(size_t)e*4] = make_float4(ae[0],ae[1],ae[2],ae[3]);
            g_tae2[e] = a2;
        }
    }
#pragma unroll
    for(int off=16; off; off>>=1)
#pragma unroll
        for(int i=0;i<16;i++) acc[i] += __shfl_xor_sync(0xffffffffu, acc[i], off);
    if((t & 31)==0)
#pragma unroll
        for(int i=0;i<16;i++) atomicAdd(&g_sum_ea[i], acc[i]);
}

// ---------------- 3. scan (3 kernels, warp-shuffle); lae folded into scanB ----------------
__global__ void k_scanA(){
    __shared__ int wsum[8], wexc[8];
    int t = threadIdx.x, blk = blockIdx.x;
    int base = blk*1024 + t*4;
    int v0 = (base+0<Nn)?g_deg[base+0]:0;
    int v1 = (base+1<Nn)?g_deg[base+1]:0;
    int v2 = (base+2<Nn)?g_deg[base+2]:0;
    int v3 = (base+3<Nn)?g_deg[base+3]:0;
    int s = v0+v1+v2+v3;
    int lane = t&31, w = t>>5;
    int ps = s;
#pragma unroll
    for(int off=1; off<32; off<<=1){
        int n = __shfl_up_sync(0xffffffffu, ps, off);
        if(lane>=off) ps += n;
    }
    if(lane==31) wsum[w] = ps;
    __syncthreads();
    if(t==0){
        int r=0;
#pragma unroll
        for(int k=0;k<8;k++){ wexc[k]=r; r+=wsum[k]; }
        g_bsum[blk]=r;
    }
    __syncthreads();
    int run = wexc[w] + ps - s;
    if(base+0<Nn) g_off[base+0]=run; run+=v0;
    if(base+1<Nn) g_off[base+1]=run; run+=v1;
    if(base+2<Nn) g_off[base+2]=run; run+=v2;
    if(base+3<Nn) g_off[base+3]=run;
}
__global__ void k_scanB(){
    int t = threadIdx.x;
    if(t==0){
        int r=0;
        for(int b=0;b<NBLK;b++){ g_boff[b]=r; r+=g_bsum[b]; }
        g_off[Nn]=EPt;
    }
    // fused lae constants (needs g_sum_ea from pass1)
    if(t>=1 && t<5){
        int h = t-1;
        float s = 0.f;
        for(int d=0;d<16;d++) s += (g_sum_ea[d]*(1.0f/(float)Ee))*g_v1[h*16+d];
        g_lae1[h] = s;
    }
    if(t == 5){
        float s = 0.f;
        for(int d=0;d<16;d++) s += (g_sum_ea[d]*(1.0f/(float)Ee))*g_v2[d];
        g_lae2[0] = s;
    }
}
__global__ void k_scanC(){
    int blk = blockIdx.x;
    if(blk==0) return;
    int add = g_boff[blk];
    int base = blk*1024 + threadIdx.x*4;
#pragma unroll
    for(int j=0;j<4;j++)
        if(base+j < Nn) g_off[base+j] += add;
}

// ---------------- 4. scatter (pure permute) ----------------
__global__ void k_scatter(const int* __restrict__ ei){
    int e = blockIdx.x*blockDim.x + threadIdx.x;
    if(e >= EPt) return;
    int s, d; float4 ae; float ae2;
    if(e < Ee){
        s = __ldg(&ei[e]); d = __ldg(&ei[Ee + e]);
        ae = *(const float4*)&g_tae1[(size_t)e*4];
        ae2 = g_tae2[e];
    } else {
        s = d = e - Ee;
        ae = make_float4(g_lae1[0],g_lae1[1],g_lae1[2],g_lae1[3]);
        ae2 = g_lae2[0];
    }
    int pos = g_off[d] + atomicAdd(&g_cur[d], 1);
    g_ssrc[pos] = s;
    *(float4*)&g_sae1[(size_t)pos*4] = ae;
    g_sae2[pos] = ae2;
}

// ---------------- 5. SGEMM (K=128) with fused a_src/a_dst epilogue ----------------
template<int NC, bool ELU>
__global__ __launch_bounds__(256) void k_gemm(const float* __restrict__ A,
                                              const float* __restrict__ W,
                                              const float* __restrict__ abias,
                                              const float* __restrict__ atts,
                                              const float* __restrict__ attd,
                                              float* __restrict__ C,
                                              float* __restrict__ oasrc,
                                              float* __restrict__ oadst, int M){
    constexpr int CPT = NC/16;
    __shared__ float As[64*36];
    __shared__ float Ws[32*NC];
    __shared__ float as_s[NC], ad_s[NC];
    const int t  = threadIdx.x;
    const int rg = t >> 4, cg = t & 15;
    const int r0 = blockIdx.x * 64;
    if(t < NC){ as_s[t]=__ldg(&atts[t]); ad_s[t]=__ldg(&attd[t]); }
    float acc[4][CPT];
#pragma unroll
    for(int i=0;i<4;i++)
#pragma unroll
        for(int j=0;j<CPT;j++) acc[i][j]=0.f;

    for(int kc=0; kc<128; kc+=32){
#pragma unroll
        for(int i=0;i<2;i++){
            int f = t + i*256; int r = f>>3; int c4 = f&7;
            float4 v = make_float4(0.f,0.f,0.f,0.f);
            if(r0 + r < M) v = __ldg((const float4*)&A[(size_t)(r0+r)*128 + kc + c4*4]);
            if(ELU){
                float4 bb = __ldg((const float4*)&abias[kc + c4*4]);
                v.x += bb.x; v.y += bb.y; v.z += bb.z; v.w += bb.w;
                v.x = v.x>0.f ? v.x : expm1f(v.x);
                v.y = v.y>0.f ? v.y : expm1f(v.y);
                v.z = v.z>0.f ? v.z : expm1f(v.z);
                v.w = v.w>0.f ? v.w : expm1f(v.w);
            }
            float* dst = &As[r*36 + c4*4];
            dst[0]=v.x; dst[1]=v.y; dst[2]=v.z; dst[3]=v.w;
        }
#pragma unroll
        for(int f=t; f < 32*NC/4; f += 256){
            int k = f/(NC/4); int c = f%(NC/4);
            *(float4*)&Ws[k*NC + c*4] = __ldg((const float4*)&W[(size_t)(kc+k)*NC + c*4]);
        }
        __syncthreads();
#pragma unroll 4
        for(int kk=0; kk<32; kk++){
            float a0 = As[(rg*4+0)*36+kk];
            float a1 = As[(rg*4+1)*36+kk];
            float a2 = As[(rg*4+2)*36+kk];
            float a3 = As[(rg*4+3)*36+kk];
            float4 b0 = *(const float4*)&Ws[kk*NC + cg*CPT];
            acc[0][0]+=a0*b0.x; acc[0][1]+=a0*b0.y; acc[0][2]+=a0*b0.z; acc[0][3]+=a0*b0.w;
            acc[1][0]+=a1*b0.x; acc[1][1]+=a1*b0.y; acc[1][2]+=a1*b0.z; acc[1][3]+=a1*b0.w;
            acc[2][0]+=a2*b0.x; acc[2][1]+=a2*b0.y; acc[2][2]+=a2*b0.z; acc[2][3]+=a2*b0.w;
            acc[3][0]+=a3*b0.x; acc[3][1]+=a3*b0.y; acc[3][2]+=a3*b0.z; acc[3][3]+=a3*b0.w;
            if constexpr (CPT == 8){
                float4 b1 = *(const float4*)&Ws[kk*NC + cg*CPT + 4];
                acc[0][4]+=a0*b1.x; acc[0][5]+=a0*b1.y; acc[0][6]+=a0*b1.z; acc[0][7]+=a0*b1.w;
                acc[1][4]+=a1*b1.x; acc[1][5]+=a1*b1.y; acc[1][6]+=a1*b1.z; acc[1][7]+=a1*b1.w;
                acc[2][4]+=a2*b1.x; acc[2][5]+=a2*b1.y; acc[2][6]+=a2*b1.z; acc[2][7]+=a2*b1.w;
                acc[3][4]+=a3*b1.x; acc[3][5]+=a3*b1.y; acc[3][6]+=a3*b1.z; acc[3][7]+=a3*b1.w;
            }
        }
        __syncthreads();
    }
#pragma unroll
    for(int i=0;i<4;i++){
        int row = r0 + rg*4 + i;
        float ps=0.f, pd=0.f;
#pragma unroll
        for(int j=0;j<CPT;j++){
            float a = acc[i][j];
            ps += a*as_s[cg*CPT+j]; pd += a*ad_s[cg*CPT+j];
        }
        if constexpr (NC == 128){
            ps += __shfl_xor_sync(0xffffffffu, ps, 1); pd += __shfl_xor_sync(0xffffffffu, pd, 1);
            ps += __shfl_xor_sync(0xffffffffu, ps, 2); pd += __shfl_xor_sync(0xffffffffu, pd, 2);
            if((cg&3)==0 && row<M){ oasrc[row*4+(cg>>2)]=ps; oadst[row*4+(cg>>2)]=pd; }
        } else {
            ps += __shfl_xor_sync(0xffffffffu, ps, 1); pd += __shfl_xor_sync(0xffffffffu, pd, 1);
            ps += __shfl_xor_sync(0xffffffffu, ps, 2); pd += __shfl_xor_sync(0xffffffffu, pd, 2);
            ps += __shfl_xor_sync(0xffffffffu, ps, 4); pd += __shfl_xor_sync(0xffffffffu, pd, 4);
            ps += __shfl_xor_sync(0xffffffffu, ps, 8); pd += __shfl_xor_sync(0xffffffffu, pd, 8);
            if(cg==0 && row<M){ oasrc[row]=ps; oadst[row]=pd; }
        }
        if(row < M){
#pragma unroll
            for(int j4=0; j4<CPT; j4+=4){
                float4 v = make_float4(acc[i][j4],acc[i][j4+1],acc[i][j4+2],acc[i][j4+3]);
                *(float4*)&C[(size_t)row*NC + cg*CPT + j4] = v;
            }
        }
    }
}

// ---------------- 6. fused layer-1: online softmax + aggregate (warp/node, x4 unroll) ----------------
#define COMB1(a, hv) { \
    if((a) <= m){ float w=__expf((a)-m); sden+=w; \
        acc.x+=hv.x*w; acc.y+=hv.y*w; acc.z+=hv.z*w; acc.w+=hv.w*w; } \
    else { float sc=__expf(m-(a)); sden=sden*sc+1.f; \
        acc.x=acc.x*sc+hv.x; acc.y=acc.y*sc+hv.y; acc.z=acc.z*sc+hv.z; acc.w=acc.w*sc+hv.w; m=(a);} }

__global__ __launch_bounds__(256) void k_layer1(){
    int lane = threadIdx.x & 31;
    int d = (blockIdx.x*blockDim.x + threadIdx.x) >> 5;
    if(d >= Nn) return;
    int beg = g_off[d], end = g_off[d+1];
    int h = lane >> 3;
    float adst = __ldg(&g_adst1[d*4+h]);
    float m = -1e30f, sden = 0.f;
    float4 acc = make_float4(0.f,0.f,0.f,0.f);
    int i = beg;
    for(; i+4 <= end; i+=4){
        int s0=__ldg(&g_ssrc[i+0]), s1=__ldg(&g_ssrc[i+1]),
            s2=__ldg(&g_ssrc[i+2]), s3=__ldg(&g_ssrc[i+3]);
        float e0=__ldg(&g_sae1[(size_t)(i+0)*4+h]), e1=__ldg(&g_sae1[(size_t)(i+1)*4+h]),
              e2=__ldg(&g_sae1[(size_t)(i+2)*4+h]), e3=__ldg(&g_sae1[(size_t)(i+3)*4+h]);
        float a0=lrelu(__ldg(&g_asrc1[s0*4+h])+adst+e0);
        float a1=lrelu(__ldg(&g_asrc1[s1*4+h])+adst+e1);
        float a2=lrelu(__ldg(&g_asrc1[s2*4+h])+adst+e2);
        float a3=lrelu(__ldg(&g_asrc1[s3*4+h])+adst+e3);
        float4 v0=__ldg((const float4*)&g_h1[(size_t)s0*128+lane*4]);
        float4 v1=__ldg((const float4*)&g_h1[(size_t)s1*128+lane*4]);
        float4 v2=__ldg((const float4*)&g_h1[(size_t)s2*128+lane*4]);
        float4 v3=__ldg((const float4*)&g_h1[(size_t)s3*128+lane*4]);
        COMB1(a0,v0); COMB1(a1,v1); COMB1(a2,v2); COMB1(a3,v3);
    }
    for(; i<end; i++){
        int s = __ldg(&g_ssrc[i]);
        float a = lrelu(__ldg(&g_asrc1[s*4+h])+adst+__ldg(&g_sae1[(size_t)i*4+h]));
        float4 hv = __ldg((const float4*)&g_h1[(size_t)s*128+lane*4]);
        COMB1(a,hv);
    }
    float inv = 1.f/sden;
    *(float4*)&g_out1[(size_t)d*128 + lane*4] =
        make_float4(acc.x*inv, acc.y*inv, acc.z*inv, acc.w*inv);
}

// ---------------- 7. fused layer-2 + pool (warp/node, float2, x4 unroll) ----------------
#define COMB2(a, hv) { \
    if((a) <= m){ float w=__expf((a)-m); sden+=w; acc.x+=hv.x*w; acc.y+=hv.y*w; } \
    else { float sc=__expf(m-(a)); sden=sden*sc+1.f; \
        acc.x=acc.x*sc+hv.x; acc.y=acc.y*sc+hv.y; m=(a);} }

__global__ __launch_bounds__(256) void k_layer2(const int* __restrict__ batch){
    int lane = threadIdx.x & 31;
    int d = (blockIdx.x*blockDim.x + threadIdx.x) >> 5;
    if(d >= Nn) return;
    int beg = g_off[d], end = g_off[d+1];
    float adst = __ldg(&g_adst2[d]);
    float m = -1e30f, sden = 0.f;
    float2 acc = make_float2(0.f,0.f);
    int i = beg;
    for(; i+4 <= end; i+=4){
        int s0=__ldg(&g_ssrc[i+0]), s1=__ldg(&g_ssrc[i+1]),
            s2=__ldg(&g_ssrc[i+2]), s3=__ldg(&g_ssrc[i+3]);
        float a0=lrelu(__ldg(&g_asrc2[s0])+adst+__ldg(&g_sae2[i+0]));
        float a1=lrelu(__ldg(&g_asrc2[s1])+adst+__ldg(&g_sae2[i+1]));
        float a2=lrelu(__ldg(&g_asrc2[s2])+adst+__ldg(&g_sae2[i+2]));
        float a3=lrelu(__ldg(&g_asrc2[s3])+adst+__ldg(&g_sae2[i+3]));
        float2 v0=__ldg((const float2*)&g_h2[(size_t)s0*64+lane*2]);
        float2 v1=__ldg((const float2*)&g_h2[(size_t)s1*64+lane*2]);
        float2 v2=__ldg((const float2*)&g_h2[(size_t)s2*64+lane*2]);
        float2 v3=__ldg((const float2*)&g_h2[(size_t)s3*64+lane*2]);
        COMB2(a0,v0); COMB2(a1,v1); COMB2(a2,v2); COMB2(a3,v3);
    }
    for(; i<end; i++){
        int s = __ldg(&g_ssrc[i]);
        float a = lrelu(__ldg(&g_asrc2[s])+adst+__ldg(&g_sae2[i]));
        float2 hv = __ldg((const float2*)&g_h2[(size_t)s*64+lane*2]);
        COMB2(a,hv);
    }
    float inv = 1.f/sden;
    int g = __ldg(&batch[d]);
    atomicAdd((float2*)&g_pool[g*64 + lane*2], make_float2(acc.x*inv, acc.y*inv));
    if(lane==0) atomicAdd(&g_cnt[g], 1);
}

// ---------------- 8. final: mean + bias ----------------
__global__ void k_final(float* __restrict__ out, const float* __restrict__ b2){
    int i = blockIdx.x*blockDim.x + threadIdx.x;
    if(i >= Gg*64) return;
    out[i] = g_pool[i] / fmaxf((float)g_cnt[i >> 6], 1.0f) + __ldg(&b2[i & 63]);
}

// ---------------- host launcher ----------------
extern "C" void kernel_launch(void* const* d_in, const int* in_sizes, int n_in,
                              void* d_out, int out_size){
    (void)in_sizes; (void)n_in; (void)out_size;
    const float* x     = (const float*)d_in[0];
    const int*   ei    = (const int*)d_in[1];
    const float* ea    = (const float*)d_in[2];
    const int*   batch = (const int*)d_in[3];
    const float* W1    = (const float*)d_in[4];
    const float* as1   = (const float*)d_in[5];
    const float* ad1   = (const float*)d_in[6];
    const float* We1   = (const float*)d_in[7];
    const float* ae1   = (const float*)d_in[8];
    const float* b1    = (const float*)d_in[9];
    const float* W2    = (const float*)d_in[10];
    const float* as2   = (const float*)d_in[11];
    const float* ad2   = (const float*)d_in[12];
    const float* We2   = (const float*)d_in[13];
    const float* ae2   = (const float*)d_in[14];
    const float* b2    = (const float*)d_in[15];
    float*       out   = (float*)d_out;

    void *p_deg,*p_cur,*p_sum,*p_pool,*p_cnt,*p_h1,*p_out1,*p_h2;
    void *p_asrc1,*p_adst1,*p_asrc2,*p_adst2;
    cudaGetSymbolAddress(&p_deg,  g_deg);
    cudaGetSymbolAddress(&p_cur,  g_cur);
    cudaGetSymbolAddress(&p_sum,  g_sum_ea);
    cudaGetSymbolAddress(&p_pool, g_pool);
    cudaGetSymbolAddress(&p_cnt,  g_cnt);
    cudaGetSymbolAddress(&p_h1,   g_h1);
    cudaGetSymbolAddress(&p_out1, g_out1);
    cudaGetSymbolAddress(&p_h2,   g_h2);
    cudaGetSymbolAddress(&p_asrc1, g_asrc1);
    cudaGetSymbolAddress(&p_adst1, g_adst1);
    cudaGetSymbolAddress(&p_asrc2, g_asrc2);
    cudaGetSymbolAddress(&p_adst2, g_adst2);

    // fork/join resources (created per call; kernel_launch runs only a few times)
    cudaStream_t s2;
    cudaEvent_t evFork, evJoin;
    cudaStreamCreateWithFlags(&s2, cudaStreamNonBlocking);
    cudaEventCreateWithFlags(&evFork, cudaEventDisableTiming);
    cudaEventCreateWithFlags(&evJoin, cudaEventDisableTiming);

    cudaMemsetAsync(p_deg, 0, Nn*sizeof(int));
    cudaMemsetAsync(p_cur, 0, Nn*sizeof(int));
    cudaMemsetAsync(p_sum, 0, 16*sizeof(float));
    cudaMemsetAsync(p_pool,0, Gg*64*sizeof(float));
    cudaMemsetAsync(p_cnt, 0, Gg*sizeof(int));

    // fork: GEMM1 runs concurrently with edge preprocessing
    cudaEventRecord(evFork, 0);
    cudaStreamWaitEvent(s2, evFork, 0);
    k_gemm<128,false><<<(Nn+63)/64, 256, 0, s2>>>(x, W1, nullptr, as1, ad1,
                                           (float*)p_h1, (float*)p_asrc1, (float*)p_adst1, Nn);
    cudaEventRecord(evJoin, s2);

    // edge preprocessing on origin stream
    k_v<<<1, 64>>>(We1, ae1, We2, ae2);
    k_pass1<<<592, 256>>>(ea, ei);
    k_scanA<<<NBLK, 256>>>();
    k_scanB<<<1, 32>>>();
    k_scanC<<<NBLK, 256>>>();
    k_scatter<<<(EPt+255)/256, 256>>>(ei);

    // join: layer1 needs both gemm1 (h1/asrc1/adst1) and scatter (CSR)
    cudaStreamWaitEvent(0, evJoin, 0);
    k_layer1<<<(Nn*32+255)/256, 256>>>();

    k_gemm<64,true><<<(Nn+63)/64, 256>>>((float*)p_out1, W2, b1, as2, ad2,
                                         (float*)p_h2, (float*)p_asrc2, (float*)p_adst2, Nn);
    k_layer2<<<(Nn*32+255)/256, 256>>>(batch);

    k_final<<<(Gg*64+255)/256, 256>>>(out, b2);
}